// round 4
// baseline (speedup 1.0000x reference)
#include <cuda_runtime.h>
#include <cstdint>

#define NN 100000
#define EE 640000
#define HH 128
#define BN_EPS 1e-5f
#define NB 391            // ceil(NN/256)
#define GB 782            // ceil(NN/128)

// ---------------- device scratch ----------------
__device__ __align__(16) float g_agg[(size_t)NN * HH];
__device__ __align__(16) float g_y[(size_t)NN * HH];
__device__ __align__(16) float g_ws[3 * 128 * 256 * 2];   // layers 0-2: [layer][n][gk][hi,lo]
__device__ __align__(16) float g_ws1[128 * 128 * 2];      // W1: [n][k][hi,lo]
__device__ int   g_deg[NN];
__device__ int   g_off[NN + 1];
__device__ int   g_cur[NN];
__device__ int   g_ssrc[EE];
__device__ int   g_bpart[512];
__device__ int   g_bbase[512];
__device__ __align__(16) float g_colsum[HH];   // zero-init; finstats re-zeroes
__device__ __align__(16) float g_colsq[HH];
__device__ __align__(16) float g_mu[HH];
__device__ __align__(16) float g_inv[HH];

// ---------------- tf32 helpers ----------------
__device__ __forceinline__ uint32_t f2tf(float x) {
    uint32_t r;
    asm("cvt.rna.tf32.f32 %0, %1;" : "=r"(r) : "f"(x));
    return r;
}
__device__ __forceinline__ void tfsplit(float v, float& hi, float& lo) {
    uint32_t h = f2tf(v);
    hi = __uint_as_float(h);
    lo = __uint_as_float(f2tf(v - hi));
}
__device__ __forceinline__ void mma8(float* c, const uint32_t* a, uint32_t b0, uint32_t b1) {
    asm("mma.sync.aligned.m16n8k8.row.col.f32.tf32.tf32.f32 "
        "{%0,%1,%2,%3},{%4,%5,%6,%7},{%8,%9},{%0,%1,%2,%3};"
        : "+f"(c[0]), "+f"(c[1]), "+f"(c[2]), "+f"(c[3])
        : "r"(a[0]), "r"(a[1]), "r"(a[2]), "r"(a[3]), "r"(b0), "r"(b1));
}

// ---------------- prologue: weight split + zero deg/cur ----------------
// 448 blocks x 256: covers 3*128*256=98304 layer elems, 16384 W1 elems, NN zeroing
__global__ void k_split(const float* __restrict__ Wl0, const float* __restrict__ Wr0,
                        const float* __restrict__ Wl1, const float* __restrict__ Wr1,
                        const float* __restrict__ Wl2, const float* __restrict__ Wr2,
                        const float* __restrict__ W1) {
    int i = blockIdx.x * 256 + threadIdx.x;
    if (i < NN) { g_deg[i] = 0; g_cur[i] = 0; }
    if (i < 3 * 128 * 256) {
        int layer = i >> 15;            // /32768
        int r = i & 32767;
        int n = r >> 8;
        int gk = r & 255;
        const float* W;
        int k = gk;
        if (gk < 128) {
            W = (layer == 0) ? Wl0 : ((layer == 1) ? Wl1 : Wl2);
        } else {
            W = (layer == 0) ? Wr0 : ((layer == 1) ? Wr1 : Wr2);
            k = gk - 128;
        }
        float v = W[n * 128 + k];
        float hi, lo;
        tfsplit(v, hi, lo);
        g_ws[(size_t)layer * 65536 + n * 512 + gk * 2] = hi;
        g_ws[(size_t)layer * 65536 + n * 512 + gk * 2 + 1] = lo;
    } else if (i < 3 * 128 * 256 + 128 * 128) {
        int r = i - 98304;
        int n = r >> 7, k = r & 127;
        float hi, lo;
        tfsplit(W1[n * 128 + k], hi, lo);
        g_ws1[n * 256 + k * 2] = hi;
        g_ws1[n * 256 + k * 2 + 1] = lo;
    }
}

// ---------------- CSR build ----------------
__global__ void k_count(const int* __restrict__ dst) {
    int e = blockIdx.x * blockDim.x + threadIdx.x;
    if (e < EE) atomicAdd(&g_deg[dst[e]], 1);
}

__global__ void k_part() {
    __shared__ int ws[8];
    int i = blockIdx.x * 256 + threadIdx.x;
    int v = (i < NN) ? g_deg[i] : 0;
    int lane = threadIdx.x & 31, wid = threadIdx.x >> 5;
    int s = v;
#pragma unroll
    for (int o = 16; o; o >>= 1) s += __shfl_xor_sync(0xFFFFFFFFu, s, o);
    if (lane == 0) ws[wid] = s;
    __syncthreads();
    if (threadIdx.x == 0) {
        int t = 0;
#pragma unroll
        for (int w = 0; w < 8; w++) t += ws[w];
        g_bpart[blockIdx.x] = t;
    }
}

__global__ void k_scanp() {
    __shared__ int ws[16];
    int t = threadIdx.x;
    int lane = t & 31, wid = t >> 5;
    int v = (t < NB) ? g_bpart[t] : 0;
    int incl = v;
#pragma unroll
    for (int o = 1; o < 32; o <<= 1) {
        int u = __shfl_up_sync(0xFFFFFFFFu, incl, o);
        if (lane >= o) incl += u;
    }
    if (lane == 31) ws[wid] = incl;
    __syncthreads();
    if (wid == 0 && lane < 16) {
        int u = ws[lane];
#pragma unroll
        for (int o = 1; o < 16; o <<= 1) {
            int p = __shfl_up_sync(0xFFFFu, u, o);
            if (lane >= o) u += p;
        }
        ws[lane] = u;
    }
    __syncthreads();
    int wpre = (wid > 0) ? ws[wid - 1] : 0;
    if (t < NB) g_bbase[t] = wpre + incl - v;
    if (t == 0) g_off[0] = 0;
}

__global__ void k_apply() {
    __shared__ int ws[8];
    int i = blockIdx.x * 256 + threadIdx.x;
    int lane = threadIdx.x & 31, wid = threadIdx.x >> 5;
    int v = (i < NN) ? g_deg[i] : 0;
    int incl = v;
#pragma unroll
    for (int o = 1; o < 32; o <<= 1) {
        int u = __shfl_up_sync(0xFFFFFFFFu, incl, o);
        if (lane >= o) incl += u;
    }
    if (lane == 31) ws[wid] = incl;
    __syncthreads();
    if (wid == 0 && lane < 8) {
        int u = ws[lane];
#pragma unroll
        for (int o = 1; o < 8; o <<= 1) {
            int p = __shfl_up_sync(0xFFu, u, o);
            if (lane >= o) u += p;
        }
        ws[lane] = u;
    }
    __syncthreads();
    int wpre = (wid > 0) ? ws[wid - 1] : 0;
    if (i < NN) g_off[i + 1] = g_bbase[blockIdx.x] + wpre + incl;
}

__global__ void k_bucket(const int* __restrict__ src, const int* __restrict__ dst) {
    int e = blockIdx.x * blockDim.x + threadIdx.x;
    if (e < EE) {
        int d = dst[e];
        int p = atomicAdd(&g_cur[d], 1);
        g_ssrc[g_off[d] + p] = src[e];
    }
}

// ---------------- mean aggregation (optionally fused BN+ReLU on the read) ----------------
__global__ void k_agg(const float* __restrict__ Xext, int xsel, int bn) {
    const float* X = (xsel == 0) ? Xext : g_y;
    int w = (blockIdx.x * blockDim.x + threadIdx.x) >> 5;
    int lane = threadIdx.x & 31;
    if (w >= NN) return;
    float4 m4 = make_float4(0.f, 0.f, 0.f, 0.f);
    float4 iv4 = make_float4(1.f, 1.f, 1.f, 1.f);
    if (bn) {
        m4 = *(const float4*)(g_mu + lane * 4);
        iv4 = *(const float4*)(g_inv + lane * 4);
    }
    int s = g_off[w], e = g_off[w + 1];
    float4 acc = make_float4(0.f, 0.f, 0.f, 0.f);
    float4 acc2 = make_float4(0.f, 0.f, 0.f, 0.f);
    int j = s;
    for (; j + 1 < e; j += 2) {
        int s0 = g_ssrc[j];
        int s1 = g_ssrc[j + 1];
        float4 v0 = *(const float4*)(X + (size_t)s0 * HH + lane * 4);
        float4 v1 = *(const float4*)(X + (size_t)s1 * HH + lane * 4);
        if (bn) {
            v0.x = fmaxf(0.f, (v0.x - m4.x) * iv4.x);
            v0.y = fmaxf(0.f, (v0.y - m4.y) * iv4.y);
            v0.z = fmaxf(0.f, (v0.z - m4.z) * iv4.z);
            v0.w = fmaxf(0.f, (v0.w - m4.w) * iv4.w);
            v1.x = fmaxf(0.f, (v1.x - m4.x) * iv4.x);
            v1.y = fmaxf(0.f, (v1.y - m4.y) * iv4.y);
            v1.z = fmaxf(0.f, (v1.z - m4.z) * iv4.z);
            v1.w = fmaxf(0.f, (v1.w - m4.w) * iv4.w);
        }
        acc.x += v0.x; acc.y += v0.y; acc.z += v0.z; acc.w += v0.w;
        acc2.x += v1.x; acc2.y += v1.y; acc2.z += v1.z; acc2.w += v1.w;
    }
    if (j < e) {
        int s0 = g_ssrc[j];
        float4 v0 = *(const float4*)(X + (size_t)s0 * HH + lane * 4);
        if (bn) {
            v0.x = fmaxf(0.f, (v0.x - m4.x) * iv4.x);
            v0.y = fmaxf(0.f, (v0.y - m4.y) * iv4.y);
            v0.z = fmaxf(0.f, (v0.z - m4.z) * iv4.z);
            v0.w = fmaxf(0.f, (v0.w - m4.w) * iv4.w);
        }
        acc.x += v0.x; acc.y += v0.y; acc.z += v0.z; acc.w += v0.w;
    }
    acc.x += acc2.x; acc.y += acc2.y; acc.z += acc2.z; acc.w += acc2.w;
    int d = e - s;
    float invd = (d > 0) ? (1.0f / (float)d) : 0.0f;
    acc.x *= invd; acc.y *= invd; acc.z *= invd; acc.w *= invd;
    *(float4*)(g_agg + (size_t)w * HH + lane * 4) = acc;
}

// ---------------- BN+ReLU fused load ----------------
__device__ __forceinline__ float4 ld_bn(const float* __restrict__ S, int row, int kk, int bn) {
    float4 v = *(const float4*)(S + (size_t)row * HH + kk);
    if (bn) {
        float4 m = *(const float4*)(g_mu + kk);
        float4 iv = *(const float4*)(g_inv + kk);
        v.x = fmaxf(0.f, (v.x - m.x) * iv.x);
        v.y = fmaxf(0.f, (v.y - m.y) * iv.y);
        v.z = fmaxf(0.f, (v.z - m.z) * iv.z);
        v.w = fmaxf(0.f, (v.w - m.w) * iv.w);
    }
    return v;
}

// ---------------- tensor-core SGEMM (3xTF32, pre-split operands) ----------------
// block 128x128, 8 warps (warp tile 32x64), K step 8, smem stride 24 (hi/lo interleaved)
__global__ void __launch_bounds__(256, 2) k_gemm(const float* __restrict__ Aext,
                                                 const float* __restrict__ Wsplit,
                                                 const float* __restrict__ bias,
                                                 int Ktot, int asel, int bsel,
                                                 int bnA, int bnB) {
    const float* PA = (asel == 1) ? g_agg : ((asel == 2) ? g_y : Aext);
    const float* PB = (bsel == 1) ? g_agg : ((bsel == 2) ? g_y : Aext);
    __shared__ float smA[2][128 * 24];
    __shared__ float smB[2][128 * 24];

    int tid = threadIdx.x;
    int lane = tid & 31, warp = tid >> 5;
    int wm = warp >> 1, wn = warp & 1;
    int m0 = blockIdx.x * 128;
    int nk = Ktot / 8;
    const int Wstride = Ktot * 2;

    float acc[2][8][4];
#pragma unroll
    for (int mt = 0; mt < 2; mt++)
#pragma unroll
        for (int nt = 0; nt < 8; nt++)
#pragma unroll
            for (int j = 0; j < 4; j++) acc[mt][nt][j] = 0.f;

    const int lrow = tid >> 1;          // 0..127
    const int lk = (tid & 1) * 4;       // 0 or 4
    const int grow = m0 + lrow;
    const bool rok = grow < NN;

    // A-side split store helper values
    float4 a4;
    float4 w0, w1;
    {
        int gk = lk;
        a4 = rok ? ld_bn(PA, grow, gk, bnA) : make_float4(0.f, 0.f, 0.f, 0.f);
        const float* Wp = Wsplit + (size_t)lrow * Wstride + gk * 2;
        w0 = *(const float4*)(Wp);
        w1 = *(const float4*)(Wp + 4);
    }
    {
        float4 s0, s1;
        tfsplit(a4.x, s0.x, s0.y);
        tfsplit(a4.y, s0.z, s0.w);
        tfsplit(a4.z, s1.x, s1.y);
        tfsplit(a4.w, s1.z, s1.w);
        *(float4*)(&smA[0][lrow * 24 + lk * 2]) = s0;
        *(float4*)(&smA[0][lrow * 24 + lk * 2 + 4]) = s1;
        *(float4*)(&smB[0][lrow * 24 + lk * 2]) = w0;
        *(float4*)(&smB[0][lrow * 24 + lk * 2 + 4]) = w1;
    }
    __syncthreads();

    for (int kc = 0; kc < nk; kc++) {
        if (kc + 1 < nk) {
            int gk = (kc + 1) * 8 + lk;
            if (rok) {
                if (gk >= 128) a4 = ld_bn(PB, grow, gk - 128, bnB);
                else           a4 = ld_bn(PA, grow, gk, bnA);
            } else {
                a4 = make_float4(0.f, 0.f, 0.f, 0.f);
            }
            const float* Wp = Wsplit + (size_t)lrow * Wstride + gk * 2;
            w0 = *(const float4*)(Wp);
            w1 = *(const float4*)(Wp + 4);
        }

        const float* A = smA[kc & 1];
        const float* B = smB[kc & 1];

        uint32_t ah[8], al[8];
#pragma unroll
        for (int mt = 0; mt < 2; mt++)
#pragma unroll
            for (int j = 0; j < 4; j++) {
                int row = wm * 32 + mt * 16 + (lane >> 2) + (j & 1) * 8;
                int kk = (lane & 3) + (j >> 1) * 4;
                float2 p = *(const float2*)(A + row * 24 + kk * 2);
                ah[mt * 4 + j] = __float_as_uint(p.x);
                al[mt * 4 + j] = __float_as_uint(p.y);
            }
#pragma unroll
        for (int nt = 0; nt < 8; nt++) {
            int n = wn * 64 + nt * 8 + (lane >> 2);
            int kk = lane & 3;
            float2 p0 = *(const float2*)(B + n * 24 + kk * 2);
            float2 p1 = *(const float2*)(B + n * 24 + (kk + 4) * 2);
            uint32_t bh0 = __float_as_uint(p0.x), bl0 = __float_as_uint(p0.y);
            uint32_t bh1 = __float_as_uint(p1.x), bl1 = __float_as_uint(p1.y);
#pragma unroll
            for (int mt = 0; mt < 2; mt++) {
                mma8(acc[mt][nt], ah + mt * 4, bh0, bh1);
                mma8(acc[mt][nt], ah + mt * 4, bl0, bl1);
                mma8(acc[mt][nt], al + mt * 4, bh0, bh1);
            }
        }

        if (kc + 1 < nk) {
            float* DA = smA[(kc + 1) & 1];
            float* DB = smB[(kc + 1) & 1];
            float4 s0, s1;
            tfsplit(a4.x, s0.x, s0.y);
            tfsplit(a4.y, s0.z, s0.w);
            tfsplit(a4.z, s1.x, s1.y);
            tfsplit(a4.w, s1.z, s1.w);
            *(float4*)(&DA[lrow * 24 + lk * 2]) = s0;
            *(float4*)(&DA[lrow * 24 + lk * 2 + 4]) = s1;
            *(float4*)(&DB[lrow * 24 + lk * 2]) = w0;
            *(float4*)(&DB[lrow * 24 + lk * 2 + 4]) = w1;
        }
        __syncthreads();
    }

    // ---------------- epilogue: bias, store, column stats ----------------
    float bc[16];
#pragma unroll
    for (int nt = 0; nt < 8; nt++) {
        int c0 = wn * 64 + nt * 8 + 2 * (lane & 3);
        bc[nt * 2 + 0] = bias[c0];
        bc[nt * 2 + 1] = bias[c0 + 1];
    }

    float s[16], q[16];
#pragma unroll
    for (int j = 0; j < 16; j++) { s[j] = 0.f; q[j] = 0.f; }

#pragma unroll
    for (int mt = 0; mt < 2; mt++) {
        int r0 = m0 + wm * 32 + mt * 16 + (lane >> 2);
        int r1 = r0 + 8;
        bool ok0 = r0 < NN, ok1 = r1 < NN;
#pragma unroll
        for (int nt = 0; nt < 8; nt++) {
            int c0 = wn * 64 + nt * 8 + 2 * (lane & 3);
            float o0 = acc[mt][nt][0] + bc[nt * 2 + 0];
            float o1 = acc[mt][nt][1] + bc[nt * 2 + 1];
            float o2 = acc[mt][nt][2] + bc[nt * 2 + 0];
            float o3 = acc[mt][nt][3] + bc[nt * 2 + 1];
            if (ok0) {
                *(float2*)(g_y + (size_t)r0 * HH + c0) = make_float2(o0, o1);
                s[nt * 2 + 0] += o0; q[nt * 2 + 0] += o0 * o0;
                s[nt * 2 + 1] += o1; q[nt * 2 + 1] += o1 * o1;
            }
            if (ok1) {
                *(float2*)(g_y + (size_t)r1 * HH + c0) = make_float2(o2, o3);
                s[nt * 2 + 0] += o2; q[nt * 2 + 0] += o2 * o2;
                s[nt * 2 + 1] += o3; q[nt * 2 + 1] += o3 * o3;
            }
        }
    }

#pragma unroll
    for (int j = 0; j < 16; j++) {
#pragma unroll
        for (int o = 4; o <= 16; o <<= 1) {
            s[j] += __shfl_xor_sync(0xFFFFFFFFu, s[j], o);
            q[j] += __shfl_xor_sync(0xFFFFFFFFu, q[j], o);
        }
    }

    float* stage = smA[0];   // reuse: [8 warps][128 cols]
    if (lane < 4) {
#pragma unroll
        for (int nt = 0; nt < 8; nt++) {
            int c = wn * 64 + nt * 8 + 2 * lane;
            stage[warp * 128 + c] = s[nt * 2 + 0];
            stage[warp * 128 + c + 1] = s[nt * 2 + 1];
        }
    }
    __syncthreads();
    if (tid < 128) {
        int cn = tid >> 6;
        float t = stage[(0 * 2 + cn) * 128 + tid] + stage[(1 * 2 + cn) * 128 + tid] +
                  stage[(2 * 2 + cn) * 128 + tid] + stage[(3 * 2 + cn) * 128 + tid];
        atomicAdd(&g_colsum[tid], t);
    }
    __syncthreads();
    if (lane < 4) {
#pragma unroll
        for (int nt = 0; nt < 8; nt++) {
            int c = wn * 64 + nt * 8 + 2 * lane;
            stage[warp * 128 + c] = q[nt * 2 + 0];
            stage[warp * 128 + c + 1] = q[nt * 2 + 1];
        }
    }
    __syncthreads();
    if (tid < 128) {
        int cn = tid >> 6;
        float t = stage[(0 * 2 + cn) * 128 + tid] + stage[(1 * 2 + cn) * 128 + tid] +
                  stage[(2 * 2 + cn) * 128 + tid] + stage[(3 * 2 + cn) * 128 + tid];
        atomicAdd(&g_colsq[tid], t);
    }
}

// ---------------- finalize stats (and re-zero accumulators) ----------------
__global__ void k_finstats() {
    int c = threadIdx.x;
    float mu = g_colsum[c] / (float)NN;
    float var = g_colsq[c] / (float)NN - mu * mu;
    g_mu[c] = mu;
    g_inv[c] = rsqrtf(var + BN_EPS);
    g_colsum[c] = 0.f;
    g_colsq[c] = 0.f;
}

// ---------------- final projection (fused BN+ReLU on read) ----------------
__global__ void k_final(const float* __restrict__ W2, const float* __restrict__ b2,
                        float* __restrict__ out) {
    int w = (blockIdx.x * blockDim.x + threadIdx.x) >> 5;
    int lane = threadIdx.x & 31;
    if (w >= NN) return;
    float4 m4 = *(const float4*)(g_mu + lane * 4);
    float4 iv4 = *(const float4*)(g_inv + lane * 4);
    float4 xv = *(const float4*)(g_y + (size_t)w * HH + lane * 4);
    xv.x = fmaxf(0.f, (xv.x - m4.x) * iv4.x);
    xv.y = fmaxf(0.f, (xv.y - m4.y) * iv4.y);
    xv.z = fmaxf(0.f, (xv.z - m4.z) * iv4.z);
    xv.w = fmaxf(0.f, (xv.w - m4.w) * iv4.w);
    float4 w0 = *(const float4*)(W2 + lane * 4);
    float4 w1 = *(const float4*)(W2 + HH + lane * 4);
    float d0 = xv.x * w0.x + xv.y * w0.y + xv.z * w0.z + xv.w * w0.w;
    float d1 = xv.x * w1.x + xv.y * w1.y + xv.z * w1.z + xv.w * w1.w;
#pragma unroll
    for (int o = 16; o; o >>= 1) {
        d0 += __shfl_xor_sync(0xFFFFFFFFu, d0, o);
        d1 += __shfl_xor_sync(0xFFFFFFFFu, d1, o);
    }
    if (lane == 0) {
        out[(size_t)w * 2 + 0] = d0 + b2[0];
        out[(size_t)w * 2 + 1] = d1 + b2[1];
    }
}

// ---------------- host launch ----------------
extern "C" void kernel_launch(void* const* d_in, const int* in_sizes, int n_in,
                              void* d_out, int out_size) {
    const float* x   = (const float*)d_in[0];
    const int*   ei  = (const int*)d_in[1];
    const int*   src = ei;
    const int*   dst = ei + EE;
    const float* Wl0 = (const float*)d_in[2];
    const float* bl0 = (const float*)d_in[3];
    const float* Wr0 = (const float*)d_in[4];
    const float* Wl1 = (const float*)d_in[5];
    const float* bl1 = (const float*)d_in[6];
    const float* Wr1 = (const float*)d_in[7];
    const float* Wl2 = (const float*)d_in[8];
    const float* bl2 = (const float*)d_in[9];
    const float* Wr2 = (const float*)d_in[10];
    const float* W1  = (const float*)d_in[11];
    const float* b1  = (const float*)d_in[12];
    const float* W2  = (const float*)d_in[13];
    const float* b2  = (const float*)d_in[14];

    float* ws_ptr = nullptr;
    float* ws1_ptr = nullptr;
    cudaGetSymbolAddress((void**)&ws_ptr, g_ws);
    cudaGetSymbolAddress((void**)&ws1_ptr, g_ws1);

    // prologue: weight split + zero deg/cur (448 blocks covers both ranges)
    k_split<<<448, 256>>>(Wl0, Wr0, Wl1, Wr1, Wl2, Wr2, W1);

    // CSR build
    k_count<<<(EE + 255) / 256, 256>>>(dst);
    k_part<<<NB, 256>>>();
    k_scanp<<<1, 512>>>();
    k_apply<<<NB, 256>>>();
    k_bucket<<<(EE + 255) / 256, 256>>>(src, dst);

    const int AGG_BLOCKS = (NN * 32 + 255) / 256;

    // layer 0: inputs raw x
    k_agg<<<AGG_BLOCKS, 256>>>(x, 0, 0);
    k_gemm<<<GB, 256>>>(x, ws_ptr, bl0, 256, /*asel=*/1, /*bsel=*/0, 0, 0);
    k_finstats<<<1, 128>>>();

    // layer 1
    k_agg<<<AGG_BLOCKS, 256>>>(nullptr, 1, 1);
    k_gemm<<<GB, 256>>>(nullptr, ws_ptr + 65536, bl1, 256, 1, 2, 0, 1);
    k_finstats<<<1, 128>>>();

    // layer 2
    k_agg<<<AGG_BLOCKS, 256>>>(nullptr, 1, 1);
    k_gemm<<<GB, 256>>>(nullptr, ws_ptr + 131072, bl2, 256, 1, 2, 0, 1);
    k_finstats<<<1, 128>>>();

    // MLP hidden: y = relu(bn(y2)) @ W1^T + b1, K=128
    k_gemm<<<GB, 256>>>(nullptr, ws1_ptr, b1, 128, 2, 2, 1, 1);
    k_finstats<<<1, 128>>>();

    // output projection
    k_final<<<AGG_BLOCKS, 256>>>(W2, b2, (float*)d_out);
}

// round 6
// speedup vs baseline: 1.1536x; 1.1536x over previous
#include <cuda_runtime.h>
#include <cstdint>

#define NN 100000
#define EE 640000
#define HH 128
#define BN_EPS 1e-5f
#define NB 391            // ceil(NN/256)
#define GB 782            // ceil(NN/128)

// ---------------- device scratch ----------------
__device__ __align__(16) float g_agg[(size_t)NN * HH];
__device__ __align__(16) float g_y[(size_t)NN * HH];
__device__ __align__(16) float g_wsh[3 * 128 * 256];   // layers 0-2 hi plane: [layer][n][gk] (32768/layer)
__device__ __align__(16) float g_wsl[3 * 128 * 256];   // lo plane
__device__ __align__(16) float g_ws1h[128 * 128];      // W1 hi: [n][k]
__device__ __align__(16) float g_ws1l[128 * 128];      // W1 lo
__device__ int   g_deg[NN];
__device__ int   g_off[NN + 1];
__device__ int   g_cur[NN];
__device__ int   g_ssrc[EE];
__device__ int   g_bpart[512];
__device__ int   g_bbase[512];
__device__ __align__(16) float g_colsum[HH];   // zero-init; finstats re-zeroes
__device__ __align__(16) float g_colsq[HH];
__device__ __align__(16) float g_mu[HH];
__device__ __align__(16) float g_inv[HH];

// ---------------- tf32 helpers ----------------
__device__ __forceinline__ uint32_t f2tf(float x) {
    uint32_t r;
    asm("cvt.rna.tf32.f32 %0, %1;" : "=r"(r) : "f"(x));
    return r;
}
__device__ __forceinline__ void tfsplit(float v, uint32_t& hi, uint32_t& lo) {
    hi = f2tf(v);
    lo = f2tf(v - __uint_as_float(hi));
}
__device__ __forceinline__ void mma8(float* c, const uint32_t* a, uint32_t b0, uint32_t b1) {
    asm("mma.sync.aligned.m16n8k8.row.col.f32.tf32.tf32.f32 "
        "{%0,%1,%2,%3},{%4,%5,%6,%7},{%8,%9},{%0,%1,%2,%3};"
        : "+f"(c[0]), "+f"(c[1]), "+f"(c[2]), "+f"(c[3])
        : "r"(a[0]), "r"(a[1]), "r"(a[2]), "r"(a[3]), "r"(b0), "r"(b1));
}

// ---------------- prologue: weight split into hi/lo planes + zero deg/cur ----------------
__global__ void k_split(const float* __restrict__ Wl0, const float* __restrict__ Wr0,
                        const float* __restrict__ Wl1, const float* __restrict__ Wr1,
                        const float* __restrict__ Wl2, const float* __restrict__ Wr2,
                        const float* __restrict__ W1) {
    int i = blockIdx.x * 256 + threadIdx.x;
    if (i < NN) { g_deg[i] = 0; g_cur[i] = 0; }
    if (i < 3 * 128 * 256) {
        int layer = i >> 15;
        int r = i & 32767;
        int n = r >> 8;
        int gk = r & 255;
        const float* W;
        int k = gk;
        if (gk < 128) {
            W = (layer == 0) ? Wl0 : ((layer == 1) ? Wl1 : Wl2);
        } else {
            W = (layer == 0) ? Wr0 : ((layer == 1) ? Wr1 : Wr2);
            k = gk - 128;
        }
        float v = W[n * 128 + k];
        uint32_t hi, lo;
        tfsplit(v, hi, lo);
        g_wsh[i] = __uint_as_float(hi);
        g_wsl[i] = __uint_as_float(lo);
    } else if (i < 3 * 128 * 256 + 128 * 128) {
        int r = i - 98304;
        uint32_t hi, lo;
        tfsplit(W1[r], hi, lo);
        g_ws1h[r] = __uint_as_float(hi);
        g_ws1l[r] = __uint_as_float(lo);
    }
}

// ---------------- CSR build ----------------
__global__ void k_count(const int* __restrict__ dst) {
    int e = blockIdx.x * blockDim.x + threadIdx.x;
    if (e < EE) atomicAdd(&g_deg[dst[e]], 1);
}

__global__ void k_part() {
    __shared__ int ws[8];
    int i = blockIdx.x * 256 + threadIdx.x;
    int v = (i < NN) ? g_deg[i] : 0;
    int lane = threadIdx.x & 31, wid = threadIdx.x >> 5;
    int s = v;
#pragma unroll
    for (int o = 16; o; o >>= 1) s += __shfl_xor_sync(0xFFFFFFFFu, s, o);
    if (lane == 0) ws[wid] = s;
    __syncthreads();
    if (threadIdx.x == 0) {
        int t = 0;
#pragma unroll
        for (int w = 0; w < 8; w++) t += ws[w];
        g_bpart[blockIdx.x] = t;
    }
}

__global__ void k_scanp() {
    __shared__ int ws[16];
    int t = threadIdx.x;
    int lane = t & 31, wid = t >> 5;
    int v = (t < NB) ? g_bpart[t] : 0;
    int incl = v;
#pragma unroll
    for (int o = 1; o < 32; o <<= 1) {
        int u = __shfl_up_sync(0xFFFFFFFFu, incl, o);
        if (lane >= o) incl += u;
    }
    if (lane == 31) ws[wid] = incl;
    __syncthreads();
    if (wid == 0 && lane < 16) {
        int u = ws[lane];
#pragma unroll
        for (int o = 1; o < 16; o <<= 1) {
            int p = __shfl_up_sync(0xFFFFu, u, o);
            if (lane >= o) u += p;
        }
        ws[lane] = u;
    }
    __syncthreads();
    int wpre = (wid > 0) ? ws[wid - 1] : 0;
    if (t < NB) g_bbase[t] = wpre + incl - v;
    if (t == 0) g_off[0] = 0;
}

__global__ void k_apply() {
    __shared__ int ws[8];
    int i = blockIdx.x * 256 + threadIdx.x;
    int lane = threadIdx.x & 31, wid = threadIdx.x >> 5;
    int v = (i < NN) ? g_deg[i] : 0;
    int incl = v;
#pragma unroll
    for (int o = 1; o < 32; o <<= 1) {
        int u = __shfl_up_sync(0xFFFFFFFFu, incl, o);
        if (lane >= o) incl += u;
    }
    if (lane == 31) ws[wid] = incl;
    __syncthreads();
    if (wid == 0 && lane < 8) {
        int u = ws[lane];
#pragma unroll
        for (int o = 1; o < 8; o <<= 1) {
            int p = __shfl_up_sync(0xFFu, u, o);
            if (lane >= o) u += p;
        }
        ws[lane] = u;
    }
    __syncthreads();
    int wpre = (wid > 0) ? ws[wid - 1] : 0;
    if (i < NN) g_off[i + 1] = g_bbase[blockIdx.x] + wpre + incl;
}

__global__ void k_bucket(const int* __restrict__ src, const int* __restrict__ dst) {
    int e = blockIdx.x * blockDim.x + threadIdx.x;
    if (e < EE) {
        int d = dst[e];
        int p = atomicAdd(&g_cur[d], 1);
        g_ssrc[g_off[d] + p] = src[e];
    }
}

// ---------------- mean aggregation (optionally fused BN+ReLU on the read) ----------------
__global__ void k_agg(const float* __restrict__ Xext, int xsel, int bn) {
    const float* X = (xsel == 0) ? Xext : g_y;
    int w = (blockIdx.x * blockDim.x + threadIdx.x) >> 5;
    int lane = threadIdx.x & 31;
    if (w >= NN) return;
    float4 m4 = make_float4(0.f, 0.f, 0.f, 0.f);
    float4 iv4 = make_float4(1.f, 1.f, 1.f, 1.f);
    if (bn) {
        m4 = *(const float4*)(g_mu + lane * 4);
        iv4 = *(const float4*)(g_inv + lane * 4);
    }
    int s = g_off[w], e = g_off[w + 1];
    float4 acc = make_float4(0.f, 0.f, 0.f, 0.f);
    float4 acc2 = make_float4(0.f, 0.f, 0.f, 0.f);
    int j = s;
    for (; j + 1 < e; j += 2) {
        int s0 = g_ssrc[j];
        int s1 = g_ssrc[j + 1];
        float4 v0 = *(const float4*)(X + (size_t)s0 * HH + lane * 4);
        float4 v1 = *(const float4*)(X + (size_t)s1 * HH + lane * 4);
        if (bn) {
            v0.x = fmaxf(0.f, (v0.x - m4.x) * iv4.x);
            v0.y = fmaxf(0.f, (v0.y - m4.y) * iv4.y);
            v0.z = fmaxf(0.f, (v0.z - m4.z) * iv4.z);
            v0.w = fmaxf(0.f, (v0.w - m4.w) * iv4.w);
            v1.x = fmaxf(0.f, (v1.x - m4.x) * iv4.x);
            v1.y = fmaxf(0.f, (v1.y - m4.y) * iv4.y);
            v1.z = fmaxf(0.f, (v1.z - m4.z) * iv4.z);
            v1.w = fmaxf(0.f, (v1.w - m4.w) * iv4.w);
        }
        acc.x += v0.x; acc.y += v0.y; acc.z += v0.z; acc.w += v0.w;
        acc2.x += v1.x; acc2.y += v1.y; acc2.z += v1.z; acc2.w += v1.w;
    }
    if (j < e) {
        int s0 = g_ssrc[j];
        float4 v0 = *(const float4*)(X + (size_t)s0 * HH + lane * 4);
        if (bn) {
            v0.x = fmaxf(0.f, (v0.x - m4.x) * iv4.x);
            v0.y = fmaxf(0.f, (v0.y - m4.y) * iv4.y);
            v0.z = fmaxf(0.f, (v0.z - m4.z) * iv4.z);
            v0.w = fmaxf(0.f, (v0.w - m4.w) * iv4.w);
        }
        acc.x += v0.x; acc.y += v0.y; acc.z += v0.z; acc.w += v0.w;
    }
    acc.x += acc2.x; acc.y += acc2.y; acc.z += acc2.z; acc.w += acc2.w;
    int d = e - s;
    float invd = (d > 0) ? (1.0f / (float)d) : 0.0f;
    acc.x *= invd; acc.y *= invd; acc.z *= invd; acc.w *= invd;
    *(float4*)(g_agg + (size_t)w * HH + lane * 4) = acc;
}

// ---------------- BN+ReLU fused load ----------------
__device__ __forceinline__ float4 ld_bn(const float* __restrict__ S, int row, int kk, int bn) {
    float4 v = *(const float4*)(S + (size_t)row * HH + kk);
    if (bn) {
        float4 m = *(const float4*)(g_mu + kk);
        float4 iv = *(const float4*)(g_inv + kk);
        v.x = fmaxf(0.f, (v.x - m.x) * iv.x);
        v.y = fmaxf(0.f, (v.y - m.y) * iv.y);
        v.z = fmaxf(0.f, (v.z - m.z) * iv.z);
        v.w = fmaxf(0.f, (v.w - m.w) * iv.w);
    }
    return v;
}

// ---------------- tensor-core SGEMM (3xTF32, B pre-split planes) ----------------
// block 128x128, 8 warps (warp tile 32x64), K step 8, conflict-free stride 12
__global__ void __launch_bounds__(256, 2) k_gemm(const float* __restrict__ Aext,
                                                 const float* __restrict__ Wh,
                                                 const float* __restrict__ Wl,
                                                 const float* __restrict__ bias,
                                                 int Ktot, int asel, int bsel,
                                                 int bnA, int bnB) {
    const float* PA = (asel == 1) ? g_agg : ((asel == 2) ? g_y : Aext);
    const float* PB = (bsel == 1) ? g_agg : ((bsel == 2) ? g_y : Aext);
    __shared__ float smA[2][128 * 12];
    __shared__ float smBh[2][128 * 12];
    __shared__ float smBl[2][128 * 12];

    int tid = threadIdx.x;
    int lane = tid & 31, warp = tid >> 5;
    int wm = warp >> 1, wn = warp & 1;
    int m0 = blockIdx.x * 128;
    int nk = Ktot / 8;

    float acc[2][8][4];
#pragma unroll
    for (int mt = 0; mt < 2; mt++)
#pragma unroll
        for (int nt = 0; nt < 8; nt++)
#pragma unroll
            for (int j = 0; j < 4; j++) acc[mt][nt][j] = 0.f;

    const int lrow = tid >> 1;          // 0..127
    const int lk = (tid & 1) * 4;       // 0 or 4
    const int grow = m0 + lrow;
    const bool rok = grow < NN;

    float4 a4, bh4, bl4;
    {
        int gk = lk;
        a4 = rok ? ld_bn(PA, grow, gk, bnA) : make_float4(0.f, 0.f, 0.f, 0.f);
        bh4 = *(const float4*)(Wh + (size_t)lrow * Ktot + gk);
        bl4 = *(const float4*)(Wl + (size_t)lrow * Ktot + gk);
    }
    *(float4*)(&smA[0][lrow * 12 + lk]) = a4;
    *(float4*)(&smBh[0][lrow * 12 + lk]) = bh4;
    *(float4*)(&smBl[0][lrow * 12 + lk]) = bl4;
    __syncthreads();

    for (int kc = 0; kc < nk; kc++) {
        if (kc + 1 < nk) {
            int gk = (kc + 1) * 8 + lk;
            if (rok) {
                if (gk >= 128) a4 = ld_bn(PB, grow, gk - 128, bnB);
                else           a4 = ld_bn(PA, grow, gk, bnA);
            } else {
                a4 = make_float4(0.f, 0.f, 0.f, 0.f);
            }
            bh4 = *(const float4*)(Wh + (size_t)lrow * Ktot + gk);
            bl4 = *(const float4*)(Wl + (size_t)lrow * Ktot + gk);
        }

        const float* A = smA[kc & 1];
        const float* Bh = smBh[kc & 1];
        const float* Bl = smBl[kc & 1];

        uint32_t ah[8], al[8];
#pragma unroll
        for (int mt = 0; mt < 2; mt++)
#pragma unroll
            for (int j = 0; j < 4; j++) {
                int row = wm * 32 + mt * 16 + (lane >> 2) + (j & 1) * 8;
                int kk = (lane & 3) + (j >> 1) * 4;
                tfsplit(A[row * 12 + kk], ah[mt * 4 + j], al[mt * 4 + j]);
            }
#pragma unroll
        for (int nt = 0; nt < 8; nt++) {
            int n = wn * 64 + nt * 8 + (lane >> 2);
            int kk = lane & 3;
            uint32_t bh0 = __float_as_uint(Bh[n * 12 + kk]);
            uint32_t bh1 = __float_as_uint(Bh[n * 12 + kk + 4]);
            uint32_t bl0 = __float_as_uint(Bl[n * 12 + kk]);
            uint32_t bl1 = __float_as_uint(Bl[n * 12 + kk + 4]);
#pragma unroll
            for (int mt = 0; mt < 2; mt++) {
                mma8(acc[mt][nt], ah + mt * 4, bh0, bh1);
                mma8(acc[mt][nt], ah + mt * 4, bl0, bl1);
                mma8(acc[mt][nt], al + mt * 4, bh0, bh1);
            }
        }

        if (kc + 1 < nk) {
            int nb = (kc + 1) & 1;
            *(float4*)(&smA[nb][lrow * 12 + lk]) = a4;
            *(float4*)(&smBh[nb][lrow * 12 + lk]) = bh4;
            *(float4*)(&smBl[nb][lrow * 12 + lk]) = bl4;
        }
        __syncthreads();
    }

    // ---------------- epilogue: bias, store, column stats ----------------
    float bc[16];
#pragma unroll
    for (int nt = 0; nt < 8; nt++) {
        int c0 = wn * 64 + nt * 8 + 2 * (lane & 3);
        bc[nt * 2 + 0] = bias[c0];
        bc[nt * 2 + 1] = bias[c0 + 1];
    }

    float s[16], q[16];
#pragma unroll
    for (int j = 0; j < 16; j++) { s[j] = 0.f; q[j] = 0.f; }

#pragma unroll
    for (int mt = 0; mt < 2; mt++) {
        int r0 = m0 + wm * 32 + mt * 16 + (lane >> 2);
        int r1 = r0 + 8;
        bool ok0 = r0 < NN, ok1 = r1 < NN;
#pragma unroll
        for (int nt = 0; nt < 8; nt++) {
            int c0 = wn * 64 + nt * 8 + 2 * (lane & 3);
            float o0 = acc[mt][nt][0] + bc[nt * 2 + 0];
            float o1 = acc[mt][nt][1] + bc[nt * 2 + 1];
            float o2 = acc[mt][nt][2] + bc[nt * 2 + 0];
            float o3 = acc[mt][nt][3] + bc[nt * 2 + 1];
            if (ok0) {
                *(float2*)(g_y + (size_t)r0 * HH + c0) = make_float2(o0, o1);
                s[nt * 2 + 0] += o0; q[nt * 2 + 0] += o0 * o0;
                s[nt * 2 + 1] += o1; q[nt * 2 + 1] += o1 * o1;
            }
            if (ok1) {
                *(float2*)(g_y + (size_t)r1 * HH + c0) = make_float2(o2, o3);
                s[nt * 2 + 0] += o2; q[nt * 2 + 0] += o2 * o2;
                s[nt * 2 + 1] += o3; q[nt * 2 + 1] += o3 * o3;
            }
        }
    }

#pragma unroll
    for (int j = 0; j < 16; j++) {
#pragma unroll
        for (int o = 4; o <= 16; o <<= 1) {
            s[j] += __shfl_xor_sync(0xFFFFFFFFu, s[j], o);
            q[j] += __shfl_xor_sync(0xFFFFFFFFu, q[j], o);
        }
    }

    float* stage = smA[0];   // reuse: [8 warps][128 cols]
    if (lane < 4) {
#pragma unroll
        for (int nt = 0; nt < 8; nt++) {
            int c = wn * 64 + nt * 8 + 2 * lane;
            stage[warp * 128 + c] = s[nt * 2 + 0];
            stage[warp * 128 + c + 1] = s[nt * 2 + 1];
        }
    }
    __syncthreads();
    if (tid < 128) {
        int cn = tid >> 6;
        float t = stage[(0 * 2 + cn) * 128 + tid] + stage[(1 * 2 + cn) * 128 + tid] +
                  stage[(2 * 2 + cn) * 128 + tid] + stage[(3 * 2 + cn) * 128 + tid];
        atomicAdd(&g_colsum[tid], t);
    }
    __syncthreads();
    if (lane < 4) {
#pragma unroll
        for (int nt = 0; nt < 8; nt++) {
            int c = wn * 64 + nt * 8 + 2 * lane;
            stage[warp * 128 + c] = q[nt * 2 + 0];
            stage[warp * 128 + c + 1] = q[nt * 2 + 1];
        }
    }
    __syncthreads();
    if (tid < 128) {
        int cn = tid >> 6;
        float t = stage[(0 * 2 + cn) * 128 + tid] + stage[(1 * 2 + cn) * 128 + tid] +
                  stage[(2 * 2 + cn) * 128 + tid] + stage[(3 * 2 + cn) * 128 + tid];
        atomicAdd(&g_colsq[tid], t);
    }
}

// ---------------- finalize stats (and re-zero accumulators) ----------------
__global__ void k_finstats() {
    int c = threadIdx.x;
    float mu = g_colsum[c] / (float)NN;
    float var = g_colsq[c] / (float)NN - mu * mu;
    g_mu[c] = mu;
    g_inv[c] = rsqrtf(var + BN_EPS);
    g_colsum[c] = 0.f;
    g_colsq[c] = 0.f;
}

// ---------------- final projection (fused BN+ReLU on read) ----------------
__global__ void k_final(const float* __restrict__ W2, const float* __restrict__ b2,
                        float* __restrict__ out) {
    int w = (blockIdx.x * blockDim.x + threadIdx.x) >> 5;
    int lane = threadIdx.x & 31;
    if (w >= NN) return;
    float4 m4 = *(const float4*)(g_mu + lane * 4);
    float4 iv4 = *(const float4*)(g_inv + lane * 4);
    float4 xv = *(const float4*)(g_y + (size_t)w * HH + lane * 4);
    xv.x = fmaxf(0.f, (xv.x - m4.x) * iv4.x);
    xv.y = fmaxf(0.f, (xv.y - m4.y) * iv4.y);
    xv.z = fmaxf(0.f, (xv.z - m4.z) * iv4.z);
    xv.w = fmaxf(0.f, (xv.w - m4.w) * iv4.w);
    float4 w0 = *(const float4*)(W2 + lane * 4);
    float4 w1 = *(const float4*)(W2 + HH + lane * 4);
    float d0 = xv.x * w0.x + xv.y * w0.y + xv.z * w0.z + xv.w * w0.w;
    float d1 = xv.x * w1.x + xv.y * w1.y + xv.z * w1.z + xv.w * w1.w;
#pragma unroll
    for (int o = 16; o; o >>= 1) {
        d0 += __shfl_xor_sync(0xFFFFFFFFu, d0, o);
        d1 += __shfl_xor_sync(0xFFFFFFFFu, d1, o);
    }
    if (lane == 0) {
        out[(size_t)w * 2 + 0] = d0 + b2[0];
        out[(size_t)w * 2 + 1] = d1 + b2[1];
    }
}

// ---------------- host launch ----------------
extern "C" void kernel_launch(void* const* d_in, const int* in_sizes, int n_in,
                              void* d_out, int out_size) {
    const float* x   = (const float*)d_in[0];
    const int*   ei  = (const int*)d_in[1];
    const int*   src = ei;
    const int*   dst = ei + EE;
    const float* Wl0 = (const float*)d_in[2];
    const float* bl0 = (const float*)d_in[3];
    const float* Wr0 = (const float*)d_in[4];
    const float* Wl1 = (const float*)d_in[5];
    const float* bl1 = (const float*)d_in[6];
    const float* Wr1 = (const float*)d_in[7];
    const float* Wl2 = (const float*)d_in[8];
    const float* bl2 = (const float*)d_in[9];
    const float* Wr2 = (const float*)d_in[10];
    const float* W1  = (const float*)d_in[11];
    const float* b1  = (const float*)d_in[12];
    const float* W2  = (const float*)d_in[13];
    const float* b2  = (const float*)d_in[14];

    float *wsh_ptr = nullptr, *wsl_ptr = nullptr, *ws1h_ptr = nullptr, *ws1l_ptr = nullptr;
    cudaGetSymbolAddress((void**)&wsh_ptr, g_wsh);
    cudaGetSymbolAddress((void**)&wsl_ptr, g_wsl);
    cudaGetSymbolAddress((void**)&ws1h_ptr, g_ws1h);
    cudaGetSymbolAddress((void**)&ws1l_ptr, g_ws1l);

    // prologue: weight split + zero deg/cur
    k_split<<<448, 256>>>(Wl0, Wr0, Wl1, Wr1, Wl2, Wr2, W1);

    // CSR build
    k_count<<<(EE + 255) / 256, 256>>>(dst);
    k_part<<<NB, 256>>>();
    k_scanp<<<1, 512>>>();
    k_apply<<<NB, 256>>>();
    k_bucket<<<(EE + 255) / 256, 256>>>(src, dst);

    const int AGG_BLOCKS = (NN * 32 + 255) / 256;
    const int LSTRIDE = 128 * 256;   // 32768 floats per layer per plane

    // layer 0: inputs raw x
    k_agg<<<AGG_BLOCKS, 256>>>(x, 0, 0);
    k_gemm<<<GB, 256>>>(x, wsh_ptr, wsl_ptr, bl0, 256, /*asel=*/1, /*bsel=*/0, 0, 0);
    k_finstats<<<1, 128>>>();

    // layer 1
    k_agg<<<AGG_BLOCKS, 256>>>(nullptr, 1, 1);
    k_gemm<<<GB, 256>>>(nullptr, wsh_ptr + LSTRIDE, wsl_ptr + LSTRIDE, bl1, 256, 1, 2, 0, 1);
    k_finstats<<<1, 128>>>();

    // layer 2
    k_agg<<<AGG_BLOCKS, 256>>>(nullptr, 1, 1);
    k_gemm<<<GB, 256>>>(nullptr, wsh_ptr + 2 * LSTRIDE, wsl_ptr + 2 * LSTRIDE, bl2, 256, 1, 2, 0, 1);
    k_finstats<<<1, 128>>>();

    // MLP hidden: y = relu(bn(y2)) @ W1^T + b1, K=128
    k_gemm<<<GB, 256>>>(nullptr, ws1h_ptr, ws1l_ptr, b1, 128, 2, 2, 1, 1);
    k_finstats<<<1, 128>>>();

    // output projection
    k_final<<<AGG_BLOCKS, 256>>>(W2, b2, (float*)d_out);
}